// round 12
// baseline (speedup 1.0000x reference)
#include <cuda_runtime.h>
#include <cuda_bf16.h>
#include <mma.h>
#include <math.h>
#include <stdint.h>

using namespace nvcuda;

// ---------------- problem constants ----------------
#define BB   256
#define LL   201
#define DD   1536
#define HH   64
#define NHD  2
#define DH   32
#define FF   256
#define NTOT (BB*LL)          // 51456 = 128 * 402

// output offsets (float elements)
#define OFF1 0
#define OFF2 3276800
#define OFF3 6553600
#define OFF4 9830400
#define SIMO 16416768

// weight scratch offsets (elements)
#define OFC   0
#define OMLP  98304
#define OQKV  102400
#define OWO   126976
#define OW1   135168
#define OW2   167936
#define WTOT  200704

// ---------------- scratch ----------------
__device__ float g_T1  [NTOT*HH];
__device__ float g_Tneg[NTOT*HH];
__device__ float g_emb [NTOT*HH];
__device__ float g_negE[NTOT*HH];
__device__ float g_x   [NTOT*HH];
__device__ float g_qkv [NTOT*192];
__device__ float g_attn[NTOT*HH];
__device__ float g_ff1 [NTOT*FF];
__device__ float g_xsum3[3*BB*DD];
__device__ float g_uon [BB*HH];
__device__ float g_part[402];
__device__ __nv_bfloat16 g_WHi[WTOT];
__device__ __nv_bfloat16 g_WLo[WTOT];

// ---------------- helpers ----------------
__device__ __forceinline__ float wsum(float v){
    #pragma unroll
    for (int o = 16; o; o >>= 1) v += __shfl_xor_sync(0xffffffffu, v, o);
    return v;
}
__device__ __forceinline__ float gelu_f(float x){
    float x3 = x*x*x;
    return 0.5f*x*(1.f + tanhf(0.7978845608028654f*(x + 0.044715f*x3)));
}

// ---------------- merged W prep ----------------
__global__ void wconv_all(const float* __restrict__ fc_w, const float* __restrict__ mlp_w,
                          const float* __restrict__ wqkv, const float* __restrict__ wo,
                          const float* __restrict__ w1,   const float* __restrict__ w2,
                          __nv_bfloat16* __restrict__ Hi, __nv_bfloat16* __restrict__ Lo)
{
    int idx = blockIdx.x*256 + threadIdx.x;
    if (idx >= WTOT) return;
    const float* src; int off;
    if      (idx < OMLP) { src = fc_w;  off = idx; }
    else if (idx < OQKV) { src = mlp_w; off = idx - OMLP; }
    else if (idx < OWO)  { src = wqkv;  off = idx - OQKV; }
    else if (idx < OW1)  { src = wo;    off = idx - OWO; }
    else if (idx < OW2)  { src = w1;    off = idx - OW1; }
    else                 { src = w2;    off = idx - OW2; }
    float w = src[off];
    __nv_bfloat16 h = __float2bfloat16(w);
    Hi[idx] = h;
    Lo[idx] = __float2bfloat16(w - __bfloat162float(h));
}

// ---------------- unified wmma GEMM (bf16x3, fp32 accum) ----------------
// EPI: 0 = bias only (dual-input capable: X2/out3 for second grid half)
//      1 = gelu(bias+..)
//      2 = out = LN(res + gemm + bias; gma, bta)          (MTOT == 64)
//      4 = dual: first half: emb=gelu -> out, x=LN(emb+pos) -> out2,
//                per-block cosine-sim partial -> part;
//          second half: negE=gelu -> out3
//      5 = final: xv = LN(res+gemm+bias); write output sections directly
template<int KTOT, int MTOT, int EPI>
__global__ void __launch_bounds__(256, 2) gemm_w(const float* __restrict__ X,
        const float* __restrict__ X2,
        const __nv_bfloat16* __restrict__ WHi, const __nv_bfloat16* __restrict__ WLo,
        const float* __restrict__ bias, const float* __restrict__ res,
        const float* __restrict__ gma, const float* __restrict__ bta,
        const float* __restrict__ pos,
        float* __restrict__ out, float* __restrict__ out2, float* __restrict__ out3,
        const float* __restrict__ uon, const float* __restrict__ bg2,
        const int* __restrict__ maskp, float* __restrict__ part,
        const float* __restrict__ embp, const float* __restrict__ negEp,
        float* __restrict__ obuf)
{
    extern __shared__ char smw[];
    __nv_bfloat16* Ahi = (__nv_bfloat16*)smw;       // 128*72
    __nv_bfloat16* Alo = Ahi + 128*72;
    __nv_bfloat16* Bhi = Alo + 128*72;              // 64*72
    __nv_bfloat16* Blo = Bhi + 64*72;

    const int t = threadIdx.x;
    const int w = t >> 5, lane = t & 31;
    const int wm = w >> 1, wn = w & 1;
    const bool second = (X2 != nullptr) && ((int)blockIdx.x >= ((int)gridDim.x >> 1));
    const int bx = second ? (int)blockIdx.x - ((int)gridDim.x >> 1) : (int)blockIdx.x;
    const size_t row0 = (size_t)bx * 128;
    const int cc = blockIdx.y * 64;
    const float* Xe = second ? X2 : X;

    wmma::fragment<wmma::accumulator,16,16,16,float> acc[2][2];
    #pragma unroll
    for (int mi = 0; mi < 2; mi++)
        #pragma unroll
        for (int ni = 0; ni < 2; ni++) wmma::fill_fragment(acc[mi][ni], 0.f);

    for (int kc = 0; kc < KTOT; kc += 64) {
        #pragma unroll
        for (int it = 0; it < 8; it++) {
            int idx = t + it*256;           // 0..2047 float4
            int r = idx >> 4, c4 = idx & 15;
            float4 v = *(const float4*)(Xe + (row0 + r)*KTOT + kc + c4*4);
            __nv_bfloat162 h0 = __float22bfloat162_rn(make_float2(v.x, v.y));
            __nv_bfloat162 h1 = __float22bfloat162_rn(make_float2(v.z, v.w));
            float2 f0 = __bfloat1622float2(h0);
            float2 f1 = __bfloat1622float2(h1);
            __nv_bfloat162 l0 = __float22bfloat162_rn(make_float2(v.x - f0.x, v.y - f0.y));
            __nv_bfloat162 l1 = __float22bfloat162_rn(make_float2(v.z - f1.x, v.w - f1.y));
            uint2 hv, lv;
            hv.x = *reinterpret_cast<uint32_t*>(&h0);
            hv.y = *reinterpret_cast<uint32_t*>(&h1);
            lv.x = *reinterpret_cast<uint32_t*>(&l0);
            lv.y = *reinterpret_cast<uint32_t*>(&l1);
            *(uint2*)(Ahi + r*72 + c4*4) = hv;
            *(uint2*)(Alo + r*72 + c4*4) = lv;
        }
        #pragma unroll
        for (int it = 0; it < 2; it++) {
            int idx = t + it*256;           // 0..511, 8 bf16 each
            int r = idx >> 3, c8 = idx & 7;
            uint4 vh = *(const uint4*)(WHi + (size_t)(kc + r)*MTOT + cc + c8*8);
            uint4 vl = *(const uint4*)(WLo + (size_t)(kc + r)*MTOT + cc + c8*8);
            *(uint4*)(Bhi + r*72 + c8*8) = vh;
            *(uint4*)(Blo + r*72 + c8*8) = vl;
        }
        __syncthreads();

        #pragma unroll
        for (int ks = 0; ks < 4; ks++) {
            wmma::fragment<wmma::matrix_a,16,16,16,__nv_bfloat16,wmma::row_major> ah[2], al[2];
            wmma::fragment<wmma::matrix_b,16,16,16,__nv_bfloat16,wmma::row_major> bh[2], bl[2];
            #pragma unroll
            for (int mi = 0; mi < 2; mi++) {
                wmma::load_matrix_sync(ah[mi], Ahi + (wm*32 + mi*16)*72 + ks*16, 72);
                wmma::load_matrix_sync(al[mi], Alo + (wm*32 + mi*16)*72 + ks*16, 72);
            }
            #pragma unroll
            for (int ni = 0; ni < 2; ni++) {
                wmma::load_matrix_sync(bh[ni], Bhi + (ks*16)*72 + wn*32 + ni*16, 72);
                wmma::load_matrix_sync(bl[ni], Blo + (ks*16)*72 + wn*32 + ni*16, 72);
            }
            #pragma unroll
            for (int mi = 0; mi < 2; mi++)
                #pragma unroll
                for (int ni = 0; ni < 2; ni++) {
                    wmma::mma_sync(acc[mi][ni], ah[mi], bh[ni], acc[mi][ni]);
                    wmma::mma_sync(acc[mi][ni], ah[mi], bl[ni], acc[mi][ni]);
                    wmma::mma_sync(acc[mi][ni], al[mi], bh[ni], acc[mi][ni]);
                }
        }
        __syncthreads();
    }

    if constexpr (EPI == 2 || EPI == 4 || EPI == 5) {
        float* C = (float*)smw;
        #pragma unroll
        for (int mi = 0; mi < 2; mi++)
            #pragma unroll
            for (int ni = 0; ni < 2; ni++)
                wmma::store_matrix_sync(C + (wm*32 + mi*16)*68 + wn*32 + ni*16,
                                        acc[mi][ni], 68, wmma::mem_row_major);
        __syncthreads();

        float simacc = 0.f;
        #pragma unroll 1
        for (int i = 0; i < 16; i++) {
            int r = w*16 + i;
            size_t gr = row0 + r;
            float v0 = C[r*68 + lane]      + bias[lane];
            float v1 = C[r*68 + 32 + lane] + bias[32 + lane];
            if constexpr (EPI == 2 || EPI == 5) {
                v0 += res[gr*64 + lane];
                v1 += res[gr*64 + 32 + lane];
            } else {   // EPI 4
                v0 = gelu_f(v0);
                v1 = gelu_f(v1);
                if (second) {
                    out3[gr*64 + lane]      = v0;   // negE
                    out3[gr*64 + 32 + lane] = v1;
                    continue;
                }
                out[gr*64 + lane]      = v0;   // emb
                out[gr*64 + 32 + lane] = v1;
                // fused cosine-similarity partial (emb vs m*uon + bg2)
                int b = (int)(gr / LL);
                float m = (float)maskp[gr];
                float g0 = fmaf(m, uon[b*64 + lane],      bg2[lane]);
                float g1 = fmaf(m, uon[b*64 + 32 + lane], bg2[lane+32]);
                float num = wsum(v0*g0 + v1*g1);
                float na  = wsum(v0*v0 + v1*v1);
                float nb  = wsum(g0*g0 + g1*g1);
                if (lane == 0) {
                    na = fmaxf(sqrtf(na), 1e-8f);
                    nb = fmaxf(sqrtf(nb), 1e-8f);
                    simacc += num / (na*nb);
                }
                int l = (int)(gr % LL);
                v0 += pos[l*64 + lane];
                v1 += pos[l*64 + 32 + lane];
            }
            float mean = wsum(v0 + v1) * (1.f/64.f);
            float d0 = v0 - mean, d1 = v1 - mean;
            float var = wsum(d0*d0 + d1*d1) * (1.f/64.f);
            float inv = rsqrtf(var + 1e-5f);
            float xv0 = d0*inv*gma[lane]    + bta[lane];
            float xv1 = d1*inv*gma[lane+32] + bta[lane+32];
            if constexpr (EPI == 5) {
                // final layer: write output sections directly (x not stored)
                float e0 = embp[gr*64 + lane];
                float e1 = embp[gr*64 + 32 + lane];
                obuf[OFF4 + gr*128 + lane]      = e0;
                obuf[OFF4 + gr*128 + 32 + lane] = e1;
                obuf[OFF4 + gr*128 + 64 + lane] = xv0;
                obuf[OFF4 + gr*128 + 96 + lane] = xv1;
                int l = (int)(gr % LL);
                if (l < LL-1) {
                    size_t r200 = (gr / LL)*(size_t)(LL-1) + l;
                    obuf[OFF1 + r200*64 + lane]      = xv0;
                    obuf[OFF1 + r200*64 + 32 + lane] = xv1;
                    obuf[OFF2 + r200*64 + lane]      = embp[(gr+1)*64 + lane];
                    obuf[OFF2 + r200*64 + 32 + lane] = embp[(gr+1)*64 + 32 + lane];
                    obuf[OFF3 + r200*64 + lane]      = negEp[gr*64 + lane];
                    obuf[OFF3 + r200*64 + 32 + lane] = negEp[gr*64 + 32 + lane];
                }
            } else {
                float* dst = (EPI == 2) ? out : out2;
                dst[gr*64 + lane]      = xv0;
                dst[gr*64 + 32 + lane] = xv1;
            }
        }
        if constexpr (EPI == 4) {
            if (!second) {
                __syncthreads();
                float* red = (float*)smw;
                if (lane == 0) red[w] = simacc;
                __syncthreads();
                if (t == 0) {
                    float s = 0.f;
                    #pragma unroll
                    for (int i = 0; i < 8; i++) s += red[i];
                    part[bx] = s;
                }
            }
        }
    } else {
        float* Cw = (float*)smw + w*(32*36);
        #pragma unroll
        for (int mi = 0; mi < 2; mi++)
            #pragma unroll
            for (int ni = 0; ni < 2; ni++)
                wmma::store_matrix_sync(Cw + mi*16*36 + ni*16, acc[mi][ni], 36,
                                        wmma::mem_row_major);
        __syncwarp();

        float* dst = second ? out3 : out;
        size_t gr = row0 + wm*32 + lane;
        #pragma unroll
        for (int c4 = 0; c4 < 8; c4++) {
            float v[4];
            #pragma unroll
            for (int u = 0; u < 4; u++) {
                v[u] = Cw[lane*36 + c4*4 + u] + __ldg(bias + cc + wn*32 + c4*4 + u);
                if (EPI == 1) v[u] = gelu_f(v[u]);
            }
            *(float4*)(dst + gr*MTOT + cc + wn*32 + c4*4) = make_float4(v[0],v[1],v[2],v[3]);
        }
    }
}

// ---------------- attention (unchanged) ----------------
__global__ void __launch_bounds__(256) attn_kernel(const float* __restrict__ qkv,
        const int* __restrict__ mask, float* __restrict__ O)
{
    extern __shared__ float sm[];
    float* Sc  = sm;                      // 8 * 204*8
    float* Qw  = Sc + 8*204*8;            // 8 * 256
    float* Inv = Qw + 8*256;              // 64
    float* Ks  = Inv + 64;                // 201*33
    float* Vs  = Ks + 201*33;             // 201*33
    float* Ms  = Vs + 201*33;             // 201

    int bh = blockIdx.x;
    int b = bh >> 1, h = bh & 1;
    const float* base = qkv + (size_t)b*LL*192;
    int t = threadIdx.x;

    for (int i = t; i < LL*32; i += 256) {
        int j = i >> 5, d = i & 31;
        Ks[j*33 + d] = base[j*192 + 64  + h*32 + d];
        Vs[j*33 + d] = base[j*192 + 128 + h*32 + d];
    }
    for (int i = t; i < LL; i += 256) Ms[i] = (float)mask[b*LL + i];
    __syncthreads();

    int w = t >> 5, lane = t & 31;
    float* sc = Sc + w*204*8;
    float* qw = Qw + w*256;
    const float scale = 0.17677669529663687f;

    for (int g = w; g < 26; g += 8) {
        int base_q = g*8;
        #pragma unroll
        for (int q = 0; q < 8; q++) {
            int lq = min(base_q + q, LL-1);
            qw[lane*8 + q] = base[(size_t)lq*192 + h*32 + lane];
        }
        __syncwarp();

        int jmax = min(LL, base_q + 8);

        auto scorepass = [&](int jhi) {
            for (int j0 = 0; j0 < jhi; j0 += 32) {
                int j = j0 + lane;
                if (j < jhi) {
                    float dot[8];
                    #pragma unroll
                    for (int q = 0; q < 8; q++) dot[q] = 0.f;
                    #pragma unroll
                    for (int d = 0; d < 32; d++) {
                        float kv = Ks[j*33 + d];
                        float4 qa = *(const float4*)(qw + d*8);
                        float4 qb = *(const float4*)(qw + d*8 + 4);
                        dot[0] = fmaf(kv, qa.x, dot[0]);
                        dot[1] = fmaf(kv, qa.y, dot[1]);
                        dot[2] = fmaf(kv, qa.z, dot[2]);
                        dot[3] = fmaf(kv, qa.w, dot[3]);
                        dot[4] = fmaf(kv, qb.x, dot[4]);
                        dot[5] = fmaf(kv, qb.y, dot[5]);
                        dot[6] = fmaf(kv, qb.z, dot[6]);
                        dot[7] = fmaf(kv, qb.w, dot[7]);
                    }
                    float m = Ms[j];
                    float s8[8];
                    #pragma unroll
                    for (int q = 0; q < 8; q++) {
                        int lq = min(base_q + q, LL-1);
                        bool allowed = (j <= lq) && (m > 0.f);
                        s8[q] = dot[q]*scale + (allowed ? 0.f : -1e9f);
                    }
                    *(float4*)(sc + j*8)     = make_float4(s8[0],s8[1],s8[2],s8[3]);
                    *(float4*)(sc + j*8 + 4) = make_float4(s8[4],s8[5],s8[6],s8[7]);
                }
            }
        };

        scorepass(jmax);
        __syncwarp();

        int qi = lane & 7, jo = lane >> 3;
        auto reduce_mx = [&](int jlen) {
            float mx = -INFINITY;
            for (int j = jo; j < jlen; j += 4) mx = fmaxf(mx, sc[j*8 + qi]);
            mx = fmaxf(mx, __shfl_xor_sync(0xffffffffu, mx, 8));
            mx = fmaxf(mx, __shfl_xor_sync(0xffffffffu, mx, 16));
            return mx;
        };
        float mx = reduce_mx(jmax);
        int jlen = jmax;
        if (__any_sync(0xffffffffu, mx < -1e8f)) {
            jlen = LL;
            scorepass(LL);
            __syncwarp();
            mx = reduce_mx(LL);
        }

        float s = 0.f;
        for (int j = jo; j < jlen; j += 4) {
            float e = __expf(sc[j*8 + qi] - mx);
            sc[j*8 + qi] = e;
            s += e;
        }
        s += __shfl_xor_sync(0xffffffffu, s, 8);
        s += __shfl_xor_sync(0xffffffffu, s, 16);
        if (lane < 8) Inv[w*8 + lane] = 1.f / s;
        __syncwarp();

        float acc[8];
        #pragma unroll
        for (int q = 0; q < 8; q++) acc[q] = 0.f;
        for (int j = 0; j < jlen; j++) {
            float v = Vs[j*33 + lane];
            float4 pa = *(const float4*)(sc + j*8);
            float4 pb = *(const float4*)(sc + j*8 + 4);
            acc[0] = fmaf(pa.x, v, acc[0]);
            acc[1] = fmaf(pa.y, v, acc[1]);
            acc[2] = fmaf(pa.z, v, acc[2]);
            acc[3] = fmaf(pa.w, v, acc[3]);
            acc[4] = fmaf(pb.x, v, acc[4]);
            acc[5] = fmaf(pb.y, v, acc[5]);
            acc[6] = fmaf(pb.z, v, acc[6]);
            acc[7] = fmaf(pb.w, v, acc[7]);
        }
        #pragma unroll
        for (int q = 0; q < 8; q++) {
            int lq = min(base_q + q, LL-1);
            O[((size_t)b*LL + lq)*64 + h*32 + lane] = acc[q] * Inv[w*8 + q];
        }
        __syncwarp();
    }
}

// ---------------- masked sum (3-way split, ballot-compacted, unroll-4) ----------------
__global__ void xsum_kernel(const float* __restrict__ X, const int* __restrict__ mask,
                            float* __restrict__ Xsum3)
{
    __shared__ int idxs[68];
    __shared__ int cntS;
    int b = blockIdx.x;
    int seg = blockIdx.y;
    int l0 = seg*67, l1 = min(LL, l0 + 67);
    int t = threadIdx.x;

    if (t < 32) {
        int c = 0;
        for (int basel = l0; basel < l1; basel += 32) {
            int l = basel + t;
            bool on = (l < l1) && (mask[b*LL + l] != 0);
            unsigned bal = __ballot_sync(0xffffffffu, on);
            int p = c + __popc(bal & ((1u << t) - 1u));
            if (on) idxs[p] = l;
            c += __popc(bal);
        }
        if (t == 0) cntS = c;
    }
    __syncthreads();
    int n = cntS;
    int d4 = t;           // 384 threads * 4 = 1536
    const float* xb = X + (size_t)b*LL*DD;
    float4 acc = make_float4(0.f,0.f,0.f,0.f);
    int i = 0;
    for (; i + 4 <= n; i += 4) {
        float4 a0 = *(const float4*)(xb + (size_t)idxs[i  ]*DD + d4*4);
        float4 a1 = *(const float4*)(xb + (size_t)idxs[i+1]*DD + d4*4);
        float4 a2 = *(const float4*)(xb + (size_t)idxs[i+2]*DD + d4*4);
        float4 a3 = *(const float4*)(xb + (size_t)idxs[i+3]*DD + d4*4);
        acc.x += a0.x; acc.y += a0.y; acc.z += a0.z; acc.w += a0.w;
        acc.x += a1.x; acc.y += a1.y; acc.z += a1.z; acc.w += a1.w;
        acc.x += a2.x; acc.y += a2.y; acc.z += a2.z; acc.w += a2.w;
        acc.x += a3.x; acc.y += a3.y; acc.z += a3.z; acc.w += a3.w;
    }
    for (; i < n; i++) {
        float4 a0 = *(const float4*)(xb + (size_t)idxs[i]*DD + d4*4);
        acc.x += a0.x; acc.y += a0.y; acc.z += a0.z; acc.w += a0.w;
    }
    *(float4*)(Xsum3 + ((size_t)seg*BB + b)*DD + d4*4) = acc;
}

// ---------------- collapsed GNN ----------------
__global__ void gnn_kernel(const float* __restrict__ Xsum3, const int* __restrict__ mask,
                           const float* __restrict__ wg1, const float* __restrict__ bg1,
                           const float* __restrict__ wg2, float* __restrict__ uon)
{
    __shared__ float xs[DD];
    __shared__ float h1[FF];
    __shared__ int   Scnt;
    int b = blockIdx.x, t = threadIdx.x;
    for (int i = t; i < DD; i += 256)
        xs[i] = Xsum3[(size_t)b*DD + i]
              + Xsum3[((size_t)BB + b)*DD + i]
              + Xsum3[((size_t)2*BB + b)*DD + i];
    int cnt = 0;
    for (int l = t; l < LL; l += 256) cnt += mask[b*LL + l];
    if (t == 0) Scnt = 0;
    __syncthreads();
    if (cnt) atomicAdd(&Scnt, cnt);
    __syncthreads();
    float S = (float)Scnt;
    float scale = S > 0.f ? 1.f/S : 0.f;
    float mg = 0.f;
    for (int k = 0; k < DD; k++) mg += xs[k] * wg1[(size_t)k*FF + t];
    h1[t] = fmaxf(mg*scale + bg1[t], 0.f);
    __syncthreads();
    if (t < 64) {
        float u = 0.f;
        for (int f = 0; f < FF; f++) u += h1[f] * wg2[(size_t)f*64 + t];
        uon[b*64 + t] = (S > 0.f) ? u : 0.f;
    }
}

// ---------------- similarity final reduce ----------------
__global__ void sim_reduce(const float* __restrict__ partial, float* __restrict__ out)
{
    __shared__ float smem[256];
    float s = 0.f;
    for (int i = threadIdx.x; i < 402; i += 256) s += partial[i];
    smem[threadIdx.x] = s;
    __syncthreads();
    for (int o = 128; o; o >>= 1) {
        if (threadIdx.x < o) smem[threadIdx.x] += smem[threadIdx.x + o];
        __syncthreads();
    }
    if (threadIdx.x == 0) out[0] = smem[0] / (float)(LL*BB);
}

// ---------------- host ----------------
template <typename T>
static void* symaddr_v(T& sym){ void* p = nullptr; cudaGetSymbolAddress(&p, sym); return p; }

extern "C" void kernel_launch(void* const* d_in, const int* in_sizes, int n_in,
                              void* d_out, int out_size)
{
    const float* inter = (const float*)d_in[0];
    const float* neg   = (const float*)d_in[1];
    const float* fc_w  = (const float*)d_in[2];
    const float* fc_b  = (const float*)d_in[3];
    const float* mlp_w = (const float*)d_in[4];
    const float* mlp_b = (const float*)d_in[5];
    const float* pos   = (const float*)d_in[6];
    const float* ln0g  = (const float*)d_in[7];
    const float* ln0b  = (const float*)d_in[8];
    const float* wqkv  = (const float*)d_in[9];
    const float* bqkv  = (const float*)d_in[10];
    const float* wo    = (const float*)d_in[11];
    const float* bo    = (const float*)d_in[12];
    const float* ln1g  = (const float*)d_in[13];
    const float* ln1b  = (const float*)d_in[14];
    const float* w1    = (const float*)d_in[15];
    const float* b1    = (const float*)d_in[16];
    const float* w2    = (const float*)d_in[17];
    const float* b2    = (const float*)d_in[18];
    const float* ln2g  = (const float*)d_in[19];
    const float* ln2b  = (const float*)d_in[20];
    const float* wg1   = (const float*)d_in[21];
    const float* bg1   = (const float*)d_in[22];
    const float* wg2   = (const float*)d_in[23];
    const float* bg2   = (const float*)d_in[24];
    const int*   mask  = (const int*)d_in[25];
    float* out = (float*)d_out;

    float* T1   = (float*)symaddr_v(g_T1);
    float* Tneg = (float*)symaddr_v(g_Tneg);
    float* emb  = (float*)symaddr_v(g_emb);
    float* negE = (float*)symaddr_v(g_negE);
    float* x    = (float*)symaddr_v(g_x);
    float* qkvb = (float*)symaddr_v(g_qkv);
    float* attO = (float*)symaddr_v(g_attn);
    float* ff1  = (float*)symaddr_v(g_ff1);
    float* Xs3  = (float*)symaddr_v(g_xsum3);
    float* uon  = (float*)symaddr_v(g_uon);
    float* part = (float*)symaddr_v(g_part);
    __nv_bfloat16* WHi = (__nv_bfloat16*)symaddr_v(g_WHi);
    __nv_bfloat16* WLo = (__nv_bfloat16*)symaddr_v(g_WLo);

    const int SMEM_W = (2*128*72 + 2*64*72) * 2;  // 55296
    const int SMEM_A = (8*204*8 + 8*256 + 64 + 201*33*2 + 201) * 4; // 114540

    cudaFuncSetAttribute((const void*)gemm_w<1536,64,0>,
                         cudaFuncAttributeMaxDynamicSharedMemorySize, SMEM_W);
    cudaFuncSetAttribute((const void*)gemm_w<64,64,4>,
                         cudaFuncAttributeMaxDynamicSharedMemorySize, SMEM_W);
    cudaFuncSetAttribute((const void*)gemm_w<64,192,0>,
                         cudaFuncAttributeMaxDynamicSharedMemorySize, SMEM_W);
    cudaFuncSetAttribute((const void*)gemm_w<64,64,2>,
                         cudaFuncAttributeMaxDynamicSharedMemorySize, SMEM_W);
    cudaFuncSetAttribute((const void*)gemm_w<64,256,1>,
                         cudaFuncAttributeMaxDynamicSharedMemorySize, SMEM_W);
    cudaFuncSetAttribute((const void*)gemm_w<256,64,2>,
                         cudaFuncAttributeMaxDynamicSharedMemorySize, SMEM_W);
    cudaFuncSetAttribute((const void*)gemm_w<256,64,5>,
                         cudaFuncAttributeMaxDynamicSharedMemorySize, SMEM_W);
    cudaFuncSetAttribute((const void*)attn_kernel,
                         cudaFuncAttributeMaxDynamicSharedMemorySize, SMEM_A);

    const int GT = NTOT/128;   // 402

    // weight conversion
    wconv_all<<<(WTOT+255)/256, 256>>>(fc_w, mlp_w, wqkv, wo, w1, w2, WHi, WLo);

    // GNN branch first (uon needed by fused-sim mlp head)
    xsum_kernel<<<dim3(BB,3), 384>>>(inter, mask, Xs3);
    gnn_kernel<<<BB, 256>>>(Xs3, mask, wg1, bg1, wg2, uon);

    // both towers in one launch (grid 804)
    gemm_w<1536,64,0><<<dim3(2*GT,1), 256, SMEM_W>>>(inter, neg, WHi+OFC, WLo+OFC, fc_b,
            nullptr, nullptr, nullptr, nullptr, T1, nullptr, Tneg,
            nullptr, nullptr, nullptr, nullptr, nullptr, nullptr, nullptr);
    // mlp heads + fused LN0 + fused cosine-sim partials
    gemm_w<64,64,4><<<dim3(2*GT,1), 256, SMEM_W>>>(T1, Tneg, WHi+OMLP, WLo+OMLP, mlp_b,
            nullptr, ln0g, ln0b, pos, emb, x, negE,
            uon, bg2, mask, part, nullptr, nullptr, nullptr);
    sim_reduce<<<1, 256>>>(part, out + SIMO);

    // encoder
    for (int i = 0; i < 2; i++) {
        gemm_w<64,192,0><<<dim3(GT,3), 256, SMEM_W>>>(x, nullptr, WHi+OQKV+(size_t)i*12288,
                WLo+OQKV+(size_t)i*12288, bqkv + i*192,
                nullptr, nullptr, nullptr, nullptr, qkvb, nullptr, nullptr,
                nullptr, nullptr, nullptr, nullptr, nullptr, nullptr, nullptr);
        attn_kernel<<<BB*NHD, 256, SMEM_A>>>(qkvb, mask, attO);
        gemm_w<64,64,2><<<dim3(GT,1), 256, SMEM_W>>>(attO, nullptr, WHi+OWO+(size_t)i*4096,
                WLo+OWO+(size_t)i*4096, bo + i*64,
                x, ln1g + i*64, ln1b + i*64, nullptr, x, nullptr, nullptr,
                nullptr, nullptr, nullptr, nullptr, nullptr, nullptr, nullptr);
        gemm_w<64,256,1><<<dim3(GT,4), 256, SMEM_W>>>(x, nullptr, WHi+OW1+(size_t)i*16384,
                WLo+OW1+(size_t)i*16384, b1 + i*256,
                nullptr, nullptr, nullptr, nullptr, ff1, nullptr, nullptr,
                nullptr, nullptr, nullptr, nullptr, nullptr, nullptr, nullptr);
        if (i == 0) {
            gemm_w<256,64,2><<<dim3(GT,1), 256, SMEM_W>>>(ff1, nullptr, WHi+OW2,
                    WLo+OW2, b2,
                    x, ln2g, ln2b, nullptr, x, nullptr, nullptr,
                    nullptr, nullptr, nullptr, nullptr, nullptr, nullptr, nullptr);
        } else {
            // final: LN fused + all output sections written directly
            gemm_w<256,64,5><<<dim3(GT,1), 256, SMEM_W>>>(ff1, nullptr, WHi+OW2+16384,
                    WLo+OW2+16384, b2 + 64,
                    x, ln2g + 64, ln2b + 64, nullptr, nullptr, nullptr, nullptr,
                    nullptr, nullptr, nullptr, nullptr, emb, negE, out);
        }
    }
}